// round 7
// baseline (speedup 1.0000x reference)
#include <cuda_runtime.h>
#include <cstdint>
#include <cstddef>

#define N_ROWS   262144
#define DDIM     64
#define QSTAGES  8
#define KCODES   1024
#define TM       256
#define TN       128
#define NTHREADS 512
#define RPAD     260            // rT row stride (floats)
#define CPAD2    258            // duplicated cbT row stride (floats), even

// shared memory layout (float units)
#define OFF_RT   0
#define OFF_CB   (OFF_RT + DDIM * RPAD)          // 16640 (double-buffered dup cb)
#define OFF_HN   (OFF_CB + 2 * DDIM * CPAD2)     // 49664
#define OFF_IDX  (OFF_HN + KCODES)               // 50688 (TM ints)
#define SMEM_FLOATS (OFF_IDX + TM)               // 50944
#define SMEM_BYTES  (SMEM_FLOATS * 4)            // 203,776 B

// hn[q][k] = XLA-emulated fp32 sum(cb*cb) (warp-tree reduction)
__device__ float g_hn[QSTAGES * KCODES];
// scratch for quantized accumulation if harness gives no qz region
__device__ float g_qscratch[(size_t)N_ROWS * DDIM];

// ---------------- packed f32x2 helpers ----------------
__device__ __forceinline__ void ffma2(unsigned long long& acc,
                                      unsigned long long a,
                                      unsigned long long b) {
    asm("fma.rn.f32x2 %0, %1, %2, %0;" : "+l"(acc) : "l"(a), "l"(b));
}
__device__ __forceinline__ float2 unpack2(unsigned long long p) {
    float2 r;
    asm("mov.b64 {%0, %1}, %2;" : "=f"(r.x), "=f"(r.y) : "l"(p));
    return r;
}
// store {v, v} (duplicated pair) to smem with one STS.64, no MOVs
__device__ __forceinline__ void sts_dup(float* addr, float v) {
    asm volatile("st.shared.v2.f32 [%0], {%1, %1};"
                 :: "r"((uint32_t)__cvta_generic_to_shared(addr)), "f"(v));
}

// ---------------- codebook norms: emulate XLA row-reduction ----------------
__global__ void hn_kernel(const float* __restrict__ cb) {
    int warp = (blockIdx.x * blockDim.x + threadIdx.x) >> 5;
    int lane = threadIdx.x & 31;
    if (warp < QSTAGES * KCODES) {
        const float* row = cb + (size_t)warp * DDIM;
        float c0 = row[lane];
        float c1 = row[lane + 32];
        float acc = __fmaf_rn(c0, c0, 0.0f);
        acc = __fmaf_rn(c1, c1, acc);
#pragma unroll
        for (int off = 16; off > 0; off >>= 1) {
            float sh = __shfl_down_sync(0xffffffffu, acc, off);
            acc = acc + sh;
        }
        if (lane == 0) g_hn[warp] = acc;
    }
}

// ---- chunk staging: gmem -> transposed DUPLICATED smem (conflict-free) ----
__device__ __forceinline__ void stage_chunk(const float* __restrict__ cbq,
                                            int c, float* __restrict__ buf,
                                            int tid) {
    int klocal = tid & 127;            // consecutive lanes -> consecutive cols
    int d0 = (tid >> 7) << 4;          // 0,16,32,48
    const float4* p = reinterpret_cast<const float4*>(
        cbq + ((size_t)(c * TN + klocal)) * DDIM + d0);
    float4 v0 = p[0], v1 = p[1], v2 = p[2], v3 = p[3];
    float* b = buf + 2 * klocal;       // dup pair for col k at float offset 2k
    sts_dup(b + (d0 +  0) * CPAD2, v0.x);
    sts_dup(b + (d0 +  1) * CPAD2, v0.y);
    sts_dup(b + (d0 +  2) * CPAD2, v0.z);
    sts_dup(b + (d0 +  3) * CPAD2, v0.w);
    sts_dup(b + (d0 +  4) * CPAD2, v1.x);
    sts_dup(b + (d0 +  5) * CPAD2, v1.y);
    sts_dup(b + (d0 +  6) * CPAD2, v1.z);
    sts_dup(b + (d0 +  7) * CPAD2, v1.w);
    sts_dup(b + (d0 +  8) * CPAD2, v2.x);
    sts_dup(b + (d0 +  9) * CPAD2, v2.y);
    sts_dup(b + (d0 + 10) * CPAD2, v2.z);
    sts_dup(b + (d0 + 11) * CPAD2, v2.w);
    sts_dup(b + (d0 + 12) * CPAD2, v3.x);
    sts_dup(b + (d0 + 13) * CPAD2, v3.y);
    sts_dup(b + (d0 + 14) * CPAD2, v3.z);
    sts_dup(b + (d0 + 15) * CPAD2, v3.w);
}

// ---------------- main fused RVQ kernel ----------------
__global__ void __launch_bounds__(NTHREADS, 1)
rvq_kernel(const float* __restrict__ x, const float* __restrict__ cb,
           float* __restrict__ qbuf, float* __restrict__ enc_f,
           int* __restrict__ enc_i) {
    extern __shared__ float smem[];
    float* s_rT  = smem + OFF_RT;
    float* s_cbT = smem + OFF_CB;
    float* s_hn  = smem + OFF_HN;
    int*   s_idx = reinterpret_cast<int*>(smem + OFF_IDX);

    const int tid = threadIdx.x;
    const int tx = tid & 15;           // 16 col lanes (cols j*16 + tx)
    const int ty = tid >> 4;           // 32 row-groups of 8
    const int row_base = blockIdx.x * TM;
    const int n2 = tid >> 1;           // update/init mapping: row
    const int dh = (tid & 1) << 5;     // and 32-d half

    // ---- init: rT = x (transposed) ----
    {
        const float4* xp = reinterpret_cast<const float4*>(
            x + (size_t)(row_base + n2) * DDIM + dh);
#pragma unroll
        for (int j = 0; j < 8; j++) {
            float4 v = xp[j];
            int dd = dh + (j << 2);
            s_rT[(dd + 0) * RPAD + n2] = v.x;
            s_rT[(dd + 1) * RPAD + n2] = v.y;
            s_rT[(dd + 2) * RPAD + n2] = v.z;
            s_rT[(dd + 3) * RPAD + n2] = v.w;
        }
    }

    for (int q = 0; q < QSTAGES; q++) {
        const float* cbq = cb + (size_t)q * (KCODES * DDIM);

#pragma unroll
        for (int i = 0; i < KCODES / NTHREADS; i++)
            s_hn[tid + i * NTHREADS] = g_hn[q * KCODES + tid + i * NTHREADS];
        __syncthreads();

        stage_chunk(cbq, 0, s_cbT, tid);
        __syncthreads();

        float bestd[8];
        int besti[8];
#pragma unroll
        for (int i = 0; i < 8; i++) { bestd[i] = 3.0e38f; besti[i] = 0x7fffffff; }

        for (int c = 0; c < KCODES / TN; c++) {
            const float* bufb = s_cbT + (c & 1) * (DDIM * CPAD2);

            // acc[rowpair rp][col j]: .x = row 2rp, .y = row 2rp+1
            unsigned long long acc[4][8];
#pragma unroll
            for (int i = 0; i < 4; i++)
#pragma unroll
                for (int j = 0; j < 8; j++) acc[i][j] = 0ULL;

            const float* rrow = s_rT + (ty << 3);
            const float* brow = bufb + (tx << 1);

            // s = sum_d r[d]*c[d]: fma, d ascending, single accumulator per
            // scalar output (per packed half) — bit-identical to SGEMM k-loop.
#pragma unroll 4
            for (int d = 0; d < DDIM; d++) {
                ulonglong2 a01 = *reinterpret_cast<const ulonglong2*>(rrow);
                ulonglong2 a23 = *reinterpret_cast<const ulonglong2*>(rrow + 4);
                unsigned long long bb[8];
#pragma unroll
                for (int j = 0; j < 8; j++)
                    bb[j] = *reinterpret_cast<const unsigned long long*>(
                        brow + (j << 5));
                unsigned long long ap[4] = {a01.x, a01.y, a23.x, a23.y};
#pragma unroll
                for (int i = 0; i < 4; i++)
#pragma unroll
                    for (int j = 0; j < 8; j++) ffma2(acc[i][j], ap[i], bb[j]);
                rrow += RPAD;
                brow += CPAD2;
            }

            // epilogue: d = fma(-2, s, hn); running strict min, cols ascending
            {
                int cb1 = c * TN + tx;
#pragma unroll
                for (int j = 0; j < 8; j++) {
                    float hnj = s_hn[cb1 + (j << 4)];
                    int col = cb1 + (j << 4);
#pragma unroll
                    for (int i = 0; i < 4; i++) {
                        float2 v = unpack2(acc[i][j]);
                        float d0v = __fmaf_rn(-2.0f, v.x, hnj);
                        float d1v = __fmaf_rn(-2.0f, v.y, hnj);
                        int r0 = 2 * i, r1 = 2 * i + 1;
                        if (d0v < bestd[r0]) { bestd[r0] = d0v; besti[r0] = col; }
                        if (d1v < bestd[r1]) { bestd[r1] = d1v; besti[r1] = col; }
                    }
                }
            }

            if (c < KCODES / TN - 1) {
                stage_chunk(cbq, c + 1, s_cbT + ((c + 1) & 1) * (DDIM * CPAD2),
                            tid);
                __syncthreads();
            }
        }

        // cross-lane argmin merge over 16 tx lanes (lexicographic (d, idx))
#pragma unroll
        for (int i = 0; i < 8; i++) {
#pragma unroll
            for (int off = 8; off > 0; off >>= 1) {
                float ov = __shfl_xor_sync(0xffffffffu, bestd[i], off);
                int oi = __shfl_xor_sync(0xffffffffu, besti[i], off);
                if (ov < bestd[i] || (ov == bestd[i] && oi < besti[i])) {
                    bestd[i] = ov;
                    besti[i] = oi;
                }
            }
        }
        if (tx == 0) {
#pragma unroll
            for (int i = 0; i < 8; i++) {
                int row = (ty << 3) + i;
                int id = besti[i];
                s_idx[row] = id;
                size_t e = (size_t)(row_base + row) * QSTAGES + q;
                if (enc_f) enc_f[e] = (float)id;
                if (enc_i) enc_i[e] = id;
            }
        }
        __syncthreads();

        // ---- update: q += cb[idx] (fp32, ref order; q lives in gmem);
        //      r = x - q ----
        {
            int id = s_idx[n2];
            const float4* cp = reinterpret_cast<const float4*>(
                cbq + (size_t)id * DDIM + dh);
            const float4* xp = reinterpret_cast<const float4*>(
                x + (size_t)(row_base + n2) * DDIM + dh);
            float* qrow = qbuf + (size_t)(row_base + n2) * DDIM + dh;
#pragma unroll
            for (int j = 0; j < 8; j++) {
                float4 cv = cp[j];
                float4 xv = xp[j];
                float4 qv;
                if (q == 0) {
                    qv.x = 0.f; qv.y = 0.f; qv.z = 0.f; qv.w = 0.f;
                } else {
                    qv = *reinterpret_cast<const float4*>(qrow + (j << 2));
                }
                float q0 = qv.x + cv.x;
                float q1 = qv.y + cv.y;
                float q2 = qv.z + cv.z;
                float q3 = qv.w + cv.w;
                float4 qo; qo.x = q0; qo.y = q1; qo.z = q2; qo.w = q3;
                *reinterpret_cast<float4*>(qrow + (j << 2)) = qo;
                int dd = dh + (j << 2);
                s_rT[(dd + 0) * RPAD + n2] = xv.x - q0;
                s_rT[(dd + 1) * RPAD + n2] = xv.y - q1;
                s_rT[(dd + 2) * RPAD + n2] = xv.z - q2;
                s_rT[(dd + 3) * RPAD + n2] = xv.w - q3;
            }
        }
        __syncthreads();
    }
    // quantized output = qbuf (accumulated in place, bit-exact ref order)
}

// ---------------- launch ----------------
extern "C" void kernel_launch(void* const* d_in, const int* in_sizes, int n_in,
                              void* d_out, int out_size) {
    const float* x = (const float*)d_in[0];
    const float* cb = (const float*)d_in[1];
    if (n_in >= 2 && in_sizes[0] == QSTAGES * KCODES * DDIM &&
        in_sizes[1] == N_ROWS * DDIM) {
        x = (const float*)d_in[1];
        cb = (const float*)d_in[0];
    }

    cudaFuncSetAttribute(rvq_kernel, cudaFuncAttributeMaxDynamicSharedMemorySize,
                         SMEM_BYTES);

    hn_kernel<<<(QSTAGES * KCODES * 32 + 255) / 256, 256>>>(cb);

    const long long enc_n = (long long)N_ROWS * QSTAGES;
    const long long qz_n = (long long)N_ROWS * DDIM;

    float* qz = nullptr;
    float* enc_f = nullptr;
    int* enc_i = nullptr;
    if ((long long)out_size == enc_n + qz_n) {
        enc_f = (float*)d_out;
        qz = (float*)d_out + enc_n;
    } else if ((long long)out_size == qz_n) {
        qz = (float*)d_out;
    } else if ((long long)out_size == enc_n) {
        enc_i = (int*)d_out;
    } else {
        enc_f = (float*)d_out;
        if ((long long)out_size >= enc_n + qz_n) qz = (float*)d_out + enc_n;
    }

    float* qbuf = qz;
    if (!qbuf) {
        cudaGetSymbolAddress((void**)&qbuf, g_qscratch);
    }

    rvq_kernel<<<N_ROWS / TM, NTHREADS, SMEM_BYTES>>>(x, cb, qbuf, enc_f, enc_i);
}

// round 8
// speedup vs baseline: 1.0803x; 1.0803x over previous
#include <cuda_runtime.h>
#include <cstdint>
#include <cstddef>

#define N_ROWS   262144
#define DDIM     64
#define QSTAGES  8
#define KCODES   1024
#define TM       128
#define TN       128
#define NTHREADS 256
#define RPAD     132            // rT row stride (floats)
#define CPAD     132            // cbT row stride (floats)

// shared memory layout (float units)
#define OFF_RT   0
#define OFF_CB   (OFF_RT + DDIM * RPAD)          // 8448 (double-buffered cb)
#define OFF_HN   (OFF_CB + 2 * DDIM * CPAD)      // 25344
#define OFF_IDX  (OFF_HN + KCODES)               // 26368 (TM ints)
#define SMEM_FLOATS (OFF_IDX + TM)               // 26496
#define SMEM_BYTES  (SMEM_FLOATS * 4)            // 105,984 B (x2 CTAs = 212KB/SM)

// hn[q][k] = XLA-emulated fp32 sum(cb*cb) (warp-tree reduction)
__device__ float g_hn[QSTAGES * KCODES];
// scratch for quantized accumulation if harness gives no qz region
__device__ float g_qscratch[(size_t)N_ROWS * DDIM];

// ---------------- packed f32x2 helpers ----------------
__device__ __forceinline__ void ffma2(unsigned long long& acc,
                                      unsigned long long a,
                                      unsigned long long b) {
    asm("fma.rn.f32x2 %0, %1, %2, %0;" : "+l"(acc) : "l"(a), "l"(b));
}
__device__ __forceinline__ unsigned long long dup2(float v) {
    unsigned long long r;
    asm("mov.b64 %0, {%1, %1};" : "=l"(r) : "f"(v));
    return r;
}
__device__ __forceinline__ float2 unpack2(unsigned long long p) {
    float2 r;
    asm("mov.b64 {%0, %1}, %2;" : "=f"(r.x), "=f"(r.y) : "l"(p));
    return r;
}

// ---------------- codebook norms: emulate XLA row-reduction ----------------
__global__ void hn_kernel(const float* __restrict__ cb) {
    int warp = (blockIdx.x * blockDim.x + threadIdx.x) >> 5;
    int lane = threadIdx.x & 31;
    if (warp < QSTAGES * KCODES) {
        const float* row = cb + (size_t)warp * DDIM;
        float c0 = row[lane];
        float c1 = row[lane + 32];
        float acc = __fmaf_rn(c0, c0, 0.0f);
        acc = __fmaf_rn(c1, c1, acc);
#pragma unroll
        for (int off = 16; off > 0; off >>= 1) {
            float sh = __shfl_down_sync(0xffffffffu, acc, off);
            acc = acc + sh;
        }
        if (lane == 0) g_hn[warp] = acc;
    }
}

// ---- chunk staging: gmem -> transposed smem (conflict-free, 256 thr) ----
__device__ __forceinline__ void stage_chunk(const float* __restrict__ cbq,
                                            int c, float* __restrict__ buf,
                                            int tid) {
    int klocal = tid & 127;            // consecutive lanes -> consecutive cols
    int dbase = (tid >> 7) << 5;       // 0 or 32
    const float4* p = reinterpret_cast<const float4*>(
        cbq + ((size_t)(c * TN + klocal)) * DDIM + dbase);
#pragma unroll
    for (int j = 0; j < 8; j++) {
        float4 v = p[j];
        int dd = dbase + (j << 2);
        buf[(dd + 0) * CPAD + klocal] = v.x;
        buf[(dd + 1) * CPAD + klocal] = v.y;
        buf[(dd + 2) * CPAD + klocal] = v.z;
        buf[(dd + 3) * CPAD + klocal] = v.w;
    }
}

// ---------------- main fused RVQ kernel ----------------
__global__ void __launch_bounds__(NTHREADS, 2)
rvq_kernel(const float* __restrict__ x, const float* __restrict__ cb,
           float* __restrict__ qbuf, float* __restrict__ enc_f,
           int* __restrict__ enc_i) {
    extern __shared__ float smem[];
    float* s_rT  = smem + OFF_RT;
    float* s_cbT = smem + OFF_CB;
    float* s_hn  = smem + OFF_HN;
    int*   s_idx = reinterpret_cast<int*>(smem + OFF_IDX);

    const int tid = threadIdx.x;
    const int tx = tid & 15;           // 16 col-groups of 8
    const int ty = tid >> 4;           // 16 row-groups of 8
    const int row_base = blockIdx.x * TM;
    const int n2 = tid >> 1;           // update/init mapping: row
    const int dh = (tid & 1) << 5;     // and 32-d half

    // ---- init: rT = x (transposed) ----
    {
        const float4* xp = reinterpret_cast<const float4*>(
            x + (size_t)(row_base + n2) * DDIM + dh);
#pragma unroll
        for (int j = 0; j < 8; j++) {
            float4 v = xp[j];
            int dd = dh + (j << 2);
            s_rT[(dd + 0) * RPAD + n2] = v.x;
            s_rT[(dd + 1) * RPAD + n2] = v.y;
            s_rT[(dd + 2) * RPAD + n2] = v.z;
            s_rT[(dd + 3) * RPAD + n2] = v.w;
        }
    }

    for (int q = 0; q < QSTAGES; q++) {
        const float* cbq = cb + (size_t)q * (KCODES * DDIM);

#pragma unroll
        for (int i = 0; i < KCODES / NTHREADS; i++)
            s_hn[tid + i * NTHREADS] = g_hn[q * KCODES + tid + i * NTHREADS];
        __syncthreads();

        stage_chunk(cbq, 0, s_cbT, tid);
        __syncthreads();

        float bestd[8];
        int besti[8];
#pragma unroll
        for (int i = 0; i < 8; i++) { bestd[i] = 3.0e38f; besti[i] = 0x7fffffff; }

        for (int c = 0; c < KCODES / TN; c++) {
            const float* bufb = s_cbT + (c & 1) * (DDIM * CPAD);

            unsigned long long acc[8][4];
#pragma unroll
            for (int i = 0; i < 8; i++)
#pragma unroll
                for (int j = 0; j < 4; j++) acc[i][j] = 0ULL;

            // s = sum_d r[d]*c[d]: fma, d ascending, single accumulator per
            // scalar output (per packed half) — bit-identical to SGEMM k-loop.
#pragma unroll 4
            for (int d = 0; d < DDIM; d++) {
                const float* rrow = s_rT + d * RPAD + (ty << 3);
                float4 a0 = *reinterpret_cast<const float4*>(rrow);
                float4 a1 = *reinterpret_cast<const float4*>(rrow + 4);
                const float* brow = bufb + d * CPAD + (tx << 2);
                ulonglong2 b0 = *reinterpret_cast<const ulonglong2*>(brow);
                ulonglong2 b1 = *reinterpret_cast<const ulonglong2*>(brow + 64);
                float av[8] = {a0.x, a0.y, a0.z, a0.w, a1.x, a1.y, a1.z, a1.w};
#pragma unroll
                for (int i = 0; i < 8; i++) {
                    unsigned long long ad = dup2(av[i]);
                    ffma2(acc[i][0], ad, b0.x);
                    ffma2(acc[i][1], ad, b0.y);
                    ffma2(acc[i][2], ad, b1.x);
                    ffma2(acc[i][3], ad, b1.y);
                }
            }

            // epilogue: d = fma(-2, s, hn); running strict min (cols ascending)
            {
                int cb1 = c * TN + (tx << 2);
                float4 h0 = *reinterpret_cast<const float4*>(s_hn + cb1);
                float4 h1 = *reinterpret_cast<const float4*>(s_hn + cb1 + 64);
                float hh[8] = {h0.x, h0.y, h0.z, h0.w, h1.x, h1.y, h1.z, h1.w};
#pragma unroll
                for (int i = 0; i < 8; i++) {
#pragma unroll
                    for (int j = 0; j < 4; j++) {
                        float2 v = unpack2(acc[i][j]);
                        int c0 = cb1 + ((j >> 1) ? 64 : 0) + ((j & 1) << 1);
                        float d0v = __fmaf_rn(-2.0f, v.x,
                                              hh[(j >> 1) * 4 + ((j & 1) << 1)]);
                        float d1v = __fmaf_rn(-2.0f, v.y,
                                              hh[(j >> 1) * 4 + ((j & 1) << 1) + 1]);
                        if (d0v < bestd[i]) { bestd[i] = d0v; besti[i] = c0; }
                        if (d1v < bestd[i]) { bestd[i] = d1v; besti[i] = c0 + 1; }
                    }
                }
            }

            if (c < KCODES / TN - 1) {
                stage_chunk(cbq, c + 1, s_cbT + ((c + 1) & 1) * (DDIM * CPAD),
                            tid);
                __syncthreads();
            }
        }

        // cross-lane argmin merge over 16 tx lanes (lexicographic (d, idx))
#pragma unroll
        for (int i = 0; i < 8; i++) {
#pragma unroll
            for (int off = 8; off > 0; off >>= 1) {
                float ov = __shfl_xor_sync(0xffffffffu, bestd[i], off);
                int oi = __shfl_xor_sync(0xffffffffu, besti[i], off);
                if (ov < bestd[i] || (ov == bestd[i] && oi < besti[i])) {
                    bestd[i] = ov;
                    besti[i] = oi;
                }
            }
        }
        if (tx == 0) {
#pragma unroll
            for (int i = 0; i < 8; i++) {
                int row = (ty << 3) + i;
                int id = besti[i];
                s_idx[row] = id;
                size_t e = (size_t)(row_base + row) * QSTAGES + q;
                if (enc_f) enc_f[e] = (float)id;
                if (enc_i) enc_i[e] = id;
            }
        }
        __syncthreads();

        // ---- update: q += cb[idx] (fp32, ref order; q lives in gmem);
        //      r = x - q ----
        {
            int id = s_idx[n2];
            const float4* cp = reinterpret_cast<const float4*>(
                cbq + (size_t)id * DDIM + dh);
            const float4* xp = reinterpret_cast<const float4*>(
                x + (size_t)(row_base + n2) * DDIM + dh);
            float* qrow = qbuf + (size_t)(row_base + n2) * DDIM + dh;
#pragma unroll
            for (int j = 0; j < 8; j++) {
                float4 cv = cp[j];
                float4 xv = xp[j];
                float4 qv;
                if (q == 0) {
                    qv.x = 0.f; qv.y = 0.f; qv.z = 0.f; qv.w = 0.f;
                } else {
                    qv = *reinterpret_cast<const float4*>(qrow + (j << 2));
                }
                float q0 = qv.x + cv.x;
                float q1 = qv.y + cv.y;
                float q2 = qv.z + cv.z;
                float q3 = qv.w + cv.w;
                float4 qo; qo.x = q0; qo.y = q1; qo.z = q2; qo.w = q3;
                *reinterpret_cast<float4*>(qrow + (j << 2)) = qo;
                int dd = dh + (j << 2);
                s_rT[(dd + 0) * RPAD + n2] = xv.x - q0;
                s_rT[(dd + 1) * RPAD + n2] = xv.y - q1;
                s_rT[(dd + 2) * RPAD + n2] = xv.z - q2;
                s_rT[(dd + 3) * RPAD + n2] = xv.w - q3;
            }
        }
        __syncthreads();
    }
    // quantized output = qbuf (accumulated in place, bit-exact ref order)
}

// ---------------- launch ----------------
extern "C" void kernel_launch(void* const* d_in, const int* in_sizes, int n_in,
                              void* d_out, int out_size) {
    const float* x = (const float*)d_in[0];
    const float* cb = (const float*)d_in[1];
    if (n_in >= 2 && in_sizes[0] == QSTAGES * KCODES * DDIM &&
        in_sizes[1] == N_ROWS * DDIM) {
        x = (const float*)d_in[1];
        cb = (const float*)d_in[0];
    }

    cudaFuncSetAttribute(rvq_kernel, cudaFuncAttributeMaxDynamicSharedMemorySize,
                         SMEM_BYTES);

    hn_kernel<<<(QSTAGES * KCODES * 32 + 255) / 256, 256>>>(cb);

    const long long enc_n = (long long)N_ROWS * QSTAGES;
    const long long qz_n = (long long)N_ROWS * DDIM;

    float* qz = nullptr;
    float* enc_f = nullptr;
    int* enc_i = nullptr;
    if ((long long)out_size == enc_n + qz_n) {
        enc_f = (float*)d_out;
        qz = (float*)d_out + enc_n;
    } else if ((long long)out_size == qz_n) {
        qz = (float*)d_out;
    } else if ((long long)out_size == enc_n) {
        enc_i = (int*)d_out;
    } else {
        enc_f = (float*)d_out;
        if ((long long)out_size >= enc_n + qz_n) qz = (float*)d_out + enc_n;
    }

    float* qbuf = qz;
    if (!qbuf) {
        cudaGetSymbolAddress((void**)&qbuf, g_qscratch);
    }

    rvq_kernel<<<N_ROWS / TM, NTHREADS, SMEM_BYTES>>>(x, cb, qbuf, enc_f, enc_i);
}